// round 14
// baseline (speedup 1.0000x reference)
#include <cuda_runtime.h>
#include <cuda_fp16.h>
#include <stdint.h>

// ---------------------------------------------------------------------------
// Problem constants
// ---------------------------------------------------------------------------
#define BB     16384
#define DI     1024
#define DH     1024
#define KTOT   2048           // Di + Dh packed K
#define NROWS  4096           // 4*Dh gate rows (permuted)
#define TM     128
#define TN     128
#define KCH    64             // K elems per pipeline chunk (fp16: 128B rows)
#define STAGES 2
#define THREADS 256
#define NKT    32             // 2048/64
// Tiles: 128 rows x 128B (64 fp16), 8 chunks of 16B, swizzle c ^= (row&7)
#define TILE_BYTES  (128 * 128)               // 16384 per operand tile
#define STAGE_BYTES (2 * TILE_BYTES)          // A, B = 32768
#define OFF_B       TILE_BYTES
#define SMEM_TOTAL  (STAGES * STAGE_BYTES)    // 65536 -> 3 CTAs/SM

// ---------------------------------------------------------------------------
// Device scratch: fp16 operands
// ---------------------------------------------------------------------------
__device__ __half g_A[(size_t)BB * KTOT];
__device__ __half g_B[(size_t)NROWS * KTOT];

// ---------------------------------------------------------------------------
// PTX helpers (base-ISA only)
// ---------------------------------------------------------------------------
__device__ __forceinline__ uint32_t smem_u32(const void* p) {
    uint32_t a;
    asm("{ .reg .u64 t; cvta.to.shared.u64 t, %1; cvt.u32.u64 %0, t; }"
        : "=r"(a) : "l"(p));
    return a;
}

__device__ __forceinline__ void cp_async16(uint32_t so, const void* gp) {
    asm volatile("cp.async.cg.shared.global [%0], [%1], 16;" :: "r"(so), "l"(gp));
}
#define CP_COMMIT() asm volatile("cp.async.commit_group;" ::: "memory")
#define CP_WAIT0()  asm volatile("cp.async.wait_group 0;" ::: "memory")

#define LDSM_X4(R, ADDR)                                                      \
    asm volatile("ldmatrix.sync.aligned.m8n8.x4.shared.b16 {%0,%1,%2,%3}, [%4];" \
                 : "=r"((R)[0]), "=r"((R)[1]), "=r"((R)[2]), "=r"((R)[3])     \
                 : "r"(ADDR))

#define MMA16816(C, A, B0, B1)                                                \
    asm volatile("mma.sync.aligned.m16n8k16.row.col.f32.f16.f16.f32 "         \
                 "{%0,%1,%2,%3},{%4,%5,%6,%7},{%8,%9},{%0,%1,%2,%3};"         \
                 : "+f"((C)[0]), "+f"((C)[1]), "+f"((C)[2]), "+f"((C)[3])     \
                 : "r"((A)[0]), "r"((A)[1]), "r"((A)[2]), "r"((A)[3]),        \
                   "r"(B0), "r"(B1))

__device__ __forceinline__ float sigf(float x)   { return 1.0f / (1.0f + __expf(-x)); }
__device__ __forceinline__ float tanh_f(float x) { return 1.0f - 2.0f / (__expf(2.0f * x) + 1.0f); }

// ---------------------------------------------------------------------------
// Prep: pack fp32 inputs into fp16 (rn) operands
// ---------------------------------------------------------------------------
__global__ void pack_A(const float* __restrict__ X, const float* __restrict__ h0) {
    size_t i4 = ((size_t)blockIdx.x * blockDim.x + threadIdx.x) * 4;
    int k = (int)(i4 & (KTOT - 1));
    size_t b = i4 >> 11;
    const float* src = (k < DI) ? (X + b * DI + k) : (h0 + b * DH + (k - DI));
    float4 v = *(const float4*)src;
    __half2* ph = (__half2*)(g_A + i4);
    ph[0] = __half2(__float2half_rn(v.x), __float2half_rn(v.y));
    ph[1] = __half2(__float2half_rn(v.z), __float2half_rn(v.w));
}

// Gate permutation matched to the mma.sync C-fragment layout:
// n = gate*1024 + d  ->  np = 64*(d>>4) + 16*((d>>2)&3) + 8*(gate>>1) + 2*(d&3) + (gate&1)
__device__ __forceinline__ int n_to_np(int n) {
    int gate = n >> 10, d = n & 1023;
    return ((d >> 4) << 6) | (((d >> 2) & 3) << 4) | ((gate >> 1) << 3)
           | ((d & 3) << 1) | (gate & 1);
}

// U part (k < 1024): 32x32 tile transpose so both read and write are coalesced.
__global__ void pack_BU(const float* __restrict__ U) {
    __shared__ float tile[32][33];
    int k0 = blockIdx.x * 32, n0 = blockIdx.y * 32;
#pragma unroll
    for (int j = threadIdx.y; j < 32; j += 8)
        tile[j][threadIdx.x] = U[(size_t)(k0 + j) * NROWS + n0 + threadIdx.x];
    __syncthreads();
#pragma unroll
    for (int j = threadIdx.y; j < 32; j += 8) {
        int np = n_to_np(n0 + j);
        g_B[(size_t)np * KTOT + k0 + threadIdx.x] = __float2half_rn(tile[threadIdx.x][j]);
    }
}

// W part (k >= 1024): W[n][k-1024] is already k-contiguous.
__global__ void pack_BW(const float* __restrict__ W) {
    size_t i = (size_t)blockIdx.x * blockDim.x + threadIdx.x;
    int kw = (int)(i & (DH - 1));
    int np = (int)(i >> 10);
    int g = ((np >> 3) & 1) * 2 + (np & 1);
    int d = ((np >> 6) << 4) + (((np >> 4) & 3) << 2) + ((np >> 1) & 3);
    int n = g * DH + d;
    g_B[(size_t)np * KTOT + DI + kw] = __float2half_rn(W[(size_t)n * DH + kw]);
}

// ---------------------------------------------------------------------------
// Single-pass fp16 GEMM; K=64 chunks, 2-stage double buffer, 3 CTAs/SM
// (cross-CTA phase stagger overlaps crossbar with tensor); fused epilogue.
// ---------------------------------------------------------------------------
__device__ __forceinline__ void load_stage(uint32_t sstage, int kt, int mbase,
                                           int nbase, int tid) {
    int kk = kt * KCH;
    int r  = tid >> 1;                     // 0..127 (row)
    int cg = (tid & 1) * 4;                // first of 4 16B chunks (8 per row)
#pragma unroll
    for (int j = 0; j < 4; j++) {
        int c = cg + j;
        uint32_t so = r * 128 + ((c ^ (r & 7)) << 4);
        cp_async16(sstage + so,         g_A + (size_t)(mbase + r) * KTOT + kk + c * 8);
        cp_async16(sstage + OFF_B + so, g_B + (size_t)(nbase + r) * KTOT + kk + c * 8);
    }
    CP_COMMIT();
}

__global__ void __launch_bounds__(THREADS, 3)
lstm_gemm(const float* __restrict__ c0, float* __restrict__ outh,
          float* __restrict__ outc) {
    extern __shared__ char smem[];
    uint32_t sbase = smem_u32(smem);
    int tid  = threadIdx.x;
    int lane = tid & 31, wid = tid >> 5;
    int wm = wid & 3, wn = wid >> 2;        // warp grid 4 (m) x 2 (n)
    int mbase = blockIdx.y * TM;
    int nbase = blockIdx.x * TN;

    // ldmatrix lane addressing (8-chunk xor swizzle, 128B rows)
    int arow = wm * 32 + (lane & 7) + ((lane >> 3) & 1) * 8;
    uint32_t abase = (uint32_t)arow * 128;
    uint32_t aswz  = (uint32_t)(arow & 7);          // invariant to +16 rows
    uint32_t abit  = (lane >> 4) & 1;
    int brow = wn * 64 + (lane & 7) + ((lane >> 4) & 1) * 8;
    uint32_t bbase = (uint32_t)brow * 128;
    uint32_t bswz  = (uint32_t)(brow & 7);          // invariant to +16 rows
    uint32_t bbit  = (lane >> 3) & 1;

    float acc[2][8][4];
#pragma unroll
    for (int mt = 0; mt < 2; mt++)
#pragma unroll
        for (int ng = 0; ng < 8; ng++)
#pragma unroll
            for (int j = 0; j < 4; j++) acc[mt][ng][j] = 0.0f;

    load_stage(sbase, 0, mbase, nbase, tid);

#pragma unroll 1
    for (int kt = 0; kt < NKT; kt++) {
        CP_WAIT0();            // stage kt&1 resident
        __syncthreads();       // recycled buffer fully consumed by all warps

        if (kt + 1 < NKT)      // prefetch overlaps this iteration's compute
            load_stage(sbase + ((kt + 1) & 1) * STAGE_BYTES, kt + 1,
                       mbase, nbase, tid);

        uint32_t sa = sbase + (kt & 1) * STAGE_BYTES;
#pragma unroll
        for (int ks = 0; ks < 4; ks++) {     // K=64 -> 4 k16 steps
            uint32_t aco = (((2 * ks + abit) ^ aswz) << 4);
            uint32_t bco = (((2 * ks + bbit) ^ bswz) << 4);
            uint32_t a0[4], a1[4];
            LDSM_X4(a0, sa + abase + aco);
            LDSM_X4(a1, sa + abase + 16 * 128 + aco);
#pragma unroll
            for (int gp = 0; gp < 4; gp++) {
                uint32_t b[4];
                LDSM_X4(b, sa + OFF_B + bbase + gp * 16 * 128 + bco);
                MMA16816(acc[0][2 * gp],     a0, b[0], b[1]);
                MMA16816(acc[1][2 * gp],     a1, b[0], b[1]);
                MMA16816(acc[0][2 * gp + 1], a0, b[2], b[3]);
                MMA16816(acc[1][2 * gp + 1], a1, b[2], b[3]);
            }
        }
    }

    // ---- Fused LSTM epilogue (gates land per-thread via B permutation) ----
    int q = lane & 3;
    int wbg = blockIdx.x * 2 + wn;
#pragma unroll
    for (int mt = 0; mt < 2; mt++) {
#pragma unroll
        for (int e = 0; e < 4; e++) {
#pragma unroll
            for (int rs = 0; rs < 2; rs++) {
                float gi = sigf(acc[mt][2 * e][rs * 2 + 0]);
                float gf = sigf(acc[mt][2 * e][rs * 2 + 1]);
                float gg = tanh_f(acc[mt][2 * e + 1][rs * 2 + 0]);
                float go = sigf(acc[mt][2 * e + 1][rs * 2 + 1]);
                int m = mbase + wm * 32 + mt * 16 + (lane >> 2) + rs * 8;
                int d = wbg * 16 + e * 4 + q;
                size_t idx = (size_t)m * DH + d;
                float c0v = __ldg(&c0[idx]);
                float cn = gf * c0v + gi * gg;
                float hn = go * tanh_f(cn);
                outh[idx] = hn;
                outc[idx] = cn;
            }
        }
    }
}

// ---------------------------------------------------------------------------
// Launch
// ---------------------------------------------------------------------------
extern "C" void kernel_launch(void* const* d_in, const int* in_sizes, int n_in,
                              void* d_out, int out_size) {
    const float* X  = (const float*)d_in[0];
    const float* h0 = (const float*)d_in[1];
    const float* c0 = (const float*)d_in[2];
    const float* U  = (const float*)d_in[3];
    const float* W  = (const float*)d_in[4];
    float* outh = (float*)d_out;
    float* outc = outh + (size_t)BB * DH;

    pack_A<<<(BB * KTOT / 4) / 256, 256>>>(X, h0);
    dim3 gbu(DI / 32, NROWS / 32);
    pack_BU<<<gbu, dim3(32, 8)>>>(U);
    pack_BW<<<(NROWS * DH) / 256, 256>>>(W);

    cudaFuncSetAttribute(lstm_gemm, cudaFuncAttributeMaxDynamicSharedMemorySize,
                         SMEM_TOTAL);
    dim3 grid(NROWS / TN, BB / TM);
    lstm_gemm<<<grid, THREADS, SMEM_TOTAL>>>(c0, outh, outc);
}

// round 15
// speedup vs baseline: 1.8369x; 1.8369x over previous
#include <cuda_runtime.h>
#include <cuda_fp16.h>
#include <stdint.h>

// ---------------------------------------------------------------------------
// Problem constants
// ---------------------------------------------------------------------------
#define BB     16384
#define DI     1024
#define DH     1024
#define KTOT   2048           // Di + Dh packed K
#define NROWS  4096           // 4*Dh gate rows (permuted)
#define TM     256
#define TN     128
#define KCH    64             // K elems per pipeline chunk (fp16: 128B rows)
#define STAGES 3
#define THREADS 512
#define NKT    32             // 2048/64
// Tiles: rows x 128B (64 fp16), 8 chunks of 16B, swizzle c ^= (row&7)
#define A_TILE_BYTES (256 * 128)              // 32768
#define B_TILE_BYTES (128 * 128)              // 16384
#define STAGE_BYTES  (A_TILE_BYTES + B_TILE_BYTES)   // 49152
#define OFF_B        A_TILE_BYTES
#define SMEM_TOTAL   (STAGES * STAGE_BYTES)   // 147456 -> 1 CTA/SM (RF-bound anyway)

// ---------------------------------------------------------------------------
// Device scratch: fp16 operands
// ---------------------------------------------------------------------------
__device__ __half g_A[(size_t)BB * KTOT];
__device__ __half g_B[(size_t)NROWS * KTOT];

// ---------------------------------------------------------------------------
// PTX helpers (base-ISA only)
// ---------------------------------------------------------------------------
__device__ __forceinline__ uint32_t smem_u32(const void* p) {
    uint32_t a;
    asm("{ .reg .u64 t; cvta.to.shared.u64 t, %1; cvt.u32.u64 %0, t; }"
        : "=r"(a) : "l"(p));
    return a;
}

__device__ __forceinline__ void cp_async16(uint32_t so, const void* gp) {
    asm volatile("cp.async.cg.shared.global [%0], [%1], 16;" :: "r"(so), "l"(gp));
}
#define CP_COMMIT() asm volatile("cp.async.commit_group;" ::: "memory")
#define CP_WAIT1()  asm volatile("cp.async.wait_group 1;" ::: "memory")

#define LDSM_X4(R, ADDR)                                                      \
    asm volatile("ldmatrix.sync.aligned.m8n8.x4.shared.b16 {%0,%1,%2,%3}, [%4];" \
                 : "=r"((R)[0]), "=r"((R)[1]), "=r"((R)[2]), "=r"((R)[3])     \
                 : "r"(ADDR))

#define MMA16816(C, A, B0, B1)                                                \
    asm volatile("mma.sync.aligned.m16n8k16.row.col.f32.f16.f16.f32 "         \
                 "{%0,%1,%2,%3},{%4,%5,%6,%7},{%8,%9},{%0,%1,%2,%3};"         \
                 : "+f"((C)[0]), "+f"((C)[1]), "+f"((C)[2]), "+f"((C)[3])     \
                 : "r"((A)[0]), "r"((A)[1]), "r"((A)[2]), "r"((A)[3]),        \
                   "r"(B0), "r"(B1))

__device__ __forceinline__ float sigf(float x)   { return 1.0f / (1.0f + __expf(-x)); }
__device__ __forceinline__ float tanh_f(float x) { return 1.0f - 2.0f / (__expf(2.0f * x) + 1.0f); }

// ---------------------------------------------------------------------------
// Prep: pack fp32 inputs into fp16 (rn) operands
// ---------------------------------------------------------------------------
__global__ void pack_A(const float* __restrict__ X, const float* __restrict__ h0) {
    size_t i4 = ((size_t)blockIdx.x * blockDim.x + threadIdx.x) * 4;
    int k = (int)(i4 & (KTOT - 1));
    size_t b = i4 >> 11;
    const float* src = (k < DI) ? (X + b * DI + k) : (h0 + b * DH + (k - DI));
    float4 v = *(const float4*)src;
    __half2* ph = (__half2*)(g_A + i4);
    ph[0] = __half2(__float2half_rn(v.x), __float2half_rn(v.y));
    ph[1] = __half2(__float2half_rn(v.z), __float2half_rn(v.w));
}

// Gate permutation matched to the mma.sync C-fragment layout:
// n = gate*1024 + d  ->  np = 64*(d>>4) + 16*((d>>2)&3) + 8*(gate>>1) + 2*(d&3) + (gate&1)
__device__ __forceinline__ int n_to_np(int n) {
    int gate = n >> 10, d = n & 1023;
    return ((d >> 4) << 6) | (((d >> 2) & 3) << 4) | ((gate >> 1) << 3)
           | ((d & 3) << 1) | (gate & 1);
}

// U part (k < 1024): 32x32 tile transpose so both read and write are coalesced.
__global__ void pack_BU(const float* __restrict__ U) {
    __shared__ float tile[32][33];
    int k0 = blockIdx.x * 32, n0 = blockIdx.y * 32;
#pragma unroll
    for (int j = threadIdx.y; j < 32; j += 8)
        tile[j][threadIdx.x] = U[(size_t)(k0 + j) * NROWS + n0 + threadIdx.x];
    __syncthreads();
#pragma unroll
    for (int j = threadIdx.y; j < 32; j += 8) {
        int np = n_to_np(n0 + j);
        g_B[(size_t)np * KTOT + k0 + threadIdx.x] = __float2half_rn(tile[threadIdx.x][j]);
    }
}

// W part (k >= 1024): W[n][k-1024] is already k-contiguous.
__global__ void pack_BW(const float* __restrict__ W) {
    size_t i = (size_t)blockIdx.x * blockDim.x + threadIdx.x;
    int kw = (int)(i & (DH - 1));
    int np = (int)(i >> 10);
    int g = ((np >> 3) & 1) * 2 + (np & 1);
    int d = ((np >> 6) << 4) + (((np >> 4) & 3) << 2) + ((np >> 1) & 3);
    int n = g * DH + d;
    g_B[(size_t)np * KTOT + DI + kw] = __float2half_rn(W[(size_t)n * DH + kw]);
}

// ---------------------------------------------------------------------------
// Single-pass fp16 GEMM; 512-thread CTA, TM=256 x TN=128 (warp grid 8x2,
// warp tile 32x64). K=64 chunks, 3 stages, prefetch distance 2, 1 CTA/SM.
// Crossbar bytes per tensor-cycle cut 27% vs the 128x128 CTA.
// ---------------------------------------------------------------------------
__device__ __forceinline__ void load_stage(uint32_t sstage, int kt, int mbase,
                                           int nbase, int tid) {
    int kk = kt * KCH;
    // A: 256 rows x 8 chunks = 2048 chunks; 4 per thread
    {
        int r  = tid >> 1;                 // 0..255
        int cg = (tid & 1) * 4;
#pragma unroll
        for (int j = 0; j < 4; j++) {
            int c = cg + j;
            uint32_t so = r * 128 + ((c ^ (r & 7)) << 4);
            cp_async16(sstage + so, g_A + (size_t)(mbase + r) * KTOT + kk + c * 8);
        }
    }
    // B: 128 rows x 8 chunks = 1024 chunks; 2 per thread
    {
        int r  = tid >> 2;                 // 0..127
        int cg = (tid & 3) * 2;
#pragma unroll
        for (int j = 0; j < 2; j++) {
            int c = cg + j;
            uint32_t so = r * 128 + ((c ^ (r & 7)) << 4);
            cp_async16(sstage + OFF_B + so, g_B + (size_t)(nbase + r) * KTOT + kk + c * 8);
        }
    }
    CP_COMMIT();
}

__global__ void __launch_bounds__(THREADS, 1)
lstm_gemm(const float* __restrict__ c0, float* __restrict__ outh,
          float* __restrict__ outc) {
    extern __shared__ char smem[];
    uint32_t sbase = smem_u32(smem);
    int tid  = threadIdx.x;
    int lane = tid & 31, wid = tid >> 5;
    int wm = wid & 7, wn = wid >> 3;        // warp grid 8 (m) x 2 (n)
    int mbase = blockIdx.y * TM;
    int nbase = blockIdx.x * TN;

    // ldmatrix lane addressing (8-chunk xor swizzle, 128B rows)
    int arow = wm * 32 + (lane & 7) + ((lane >> 3) & 1) * 8;
    uint32_t abase = (uint32_t)arow * 128;
    uint32_t aswz  = (uint32_t)(arow & 7);          // invariant to +16 rows
    uint32_t abit  = (lane >> 4) & 1;
    int brow = wn * 64 + (lane & 7) + ((lane >> 4) & 1) * 8;
    uint32_t bbase = (uint32_t)brow * 128;
    uint32_t bswz  = (uint32_t)(brow & 7);          // invariant to +16 rows
    uint32_t bbit  = (lane >> 3) & 1;

    float acc[2][8][4];
#pragma unroll
    for (int mt = 0; mt < 2; mt++)
#pragma unroll
        for (int ng = 0; ng < 8; ng++)
#pragma unroll
            for (int j = 0; j < 4; j++) acc[mt][ng][j] = 0.0f;

    load_stage(sbase, 0, mbase, nbase, tid);
    load_stage(sbase + STAGE_BYTES, 1, mbase, nbase, tid);

    int stage = 0;
#pragma unroll 1
    for (int kt = 0; kt < NKT; kt++) {
        CP_WAIT1();            // stage kt resident (issued 2 iterations ago)
        __syncthreads();       // recycled buffer fully consumed by all warps

        if (kt + 2 < NKT) {
            int snext = stage + 2; if (snext >= STAGES) snext -= STAGES;
            load_stage(sbase + snext * STAGE_BYTES, kt + 2, mbase, nbase, tid);
        } else {
            CP_COMMIT();       // dummy group keeps wait_group 1 semantics
        }

        uint32_t sa = sbase + stage * STAGE_BYTES;
#pragma unroll
        for (int ks = 0; ks < 4; ks++) {     // K=64 -> 4 k16 steps
            uint32_t aco = (((2 * ks + abit) ^ aswz) << 4);
            uint32_t bco = (((2 * ks + bbit) ^ bswz) << 4);
            uint32_t a0[4], a1[4];
            LDSM_X4(a0, sa + abase + aco);
            LDSM_X4(a1, sa + abase + 16 * 128 + aco);
#pragma unroll
            for (int gp = 0; gp < 4; gp++) {
                uint32_t b[4];
                LDSM_X4(b, sa + OFF_B + bbase + gp * 16 * 128 + bco);
                MMA16816(acc[0][2 * gp],     a0, b[0], b[1]);
                MMA16816(acc[1][2 * gp],     a1, b[0], b[1]);
                MMA16816(acc[0][2 * gp + 1], a0, b[2], b[3]);
                MMA16816(acc[1][2 * gp + 1], a1, b[2], b[3]);
            }
        }
        stage = stage + 1; if (stage >= STAGES) stage = 0;
    }

    // ---- Fused LSTM epilogue (gates land per-thread via B permutation) ----
    int q = lane & 3;
    int wbg = blockIdx.x * 2 + wn;
#pragma unroll
    for (int mt = 0; mt < 2; mt++) {
#pragma unroll
        for (int e = 0; e < 4; e++) {
#pragma unroll
            for (int rs = 0; rs < 2; rs++) {
                float gi = sigf(acc[mt][2 * e][rs * 2 + 0]);
                float gf = sigf(acc[mt][2 * e][rs * 2 + 1]);
                float gg = tanh_f(acc[mt][2 * e + 1][rs * 2 + 0]);
                float go = sigf(acc[mt][2 * e + 1][rs * 2 + 1]);
                int m = mbase + wm * 32 + mt * 16 + (lane >> 2) + rs * 8;
                int d = wbg * 16 + e * 4 + q;
                size_t idx = (size_t)m * DH + d;
                float c0v = __ldg(&c0[idx]);
                float cn = gf * c0v + gi * gg;
                float hn = go * tanh_f(cn);
                outh[idx] = hn;
                outc[idx] = cn;
            }
        }
    }
}

// ---------------------------------------------------------------------------
// Launch
// ---------------------------------------------------------------------------
extern "C" void kernel_launch(void* const* d_in, const int* in_sizes, int n_in,
                              void* d_out, int out_size) {
    const float* X  = (const float*)d_in[0];
    const float* h0 = (const float*)d_in[1];
    const float* c0 = (const float*)d_in[2];
    const float* U  = (const float*)d_in[3];
    const float* W  = (const float*)d_in[4];
    float* outh = (float*)d_out;
    float* outc = outh + (size_t)BB * DH;

    pack_A<<<(BB * KTOT / 4) / 256, 256>>>(X, h0);
    dim3 gbu(DI / 32, NROWS / 32);
    pack_BU<<<gbu, dim3(32, 8)>>>(U);
    pack_BW<<<(NROWS * DH) / 256, 256>>>(W);

    cudaFuncSetAttribute(lstm_gemm, cudaFuncAttributeMaxDynamicSharedMemorySize,
                         SMEM_TOTAL);
    dim3 grid(NROWS / TN, BB / TM);
    lstm_gemm<<<grid, THREADS, SMEM_TOTAL>>>(c0, outh, outc);
}

// round 16
// speedup vs baseline: 2.3013x; 1.2529x over previous
#include <cuda_runtime.h>
#include <cuda_fp16.h>
#include <stdint.h>

// ---------------------------------------------------------------------------
// Problem constants
// ---------------------------------------------------------------------------
#define BB     16384
#define DI     1024
#define DH     1024
#define KTOT   2048           // Di + Dh packed K
#define NROWS  4096           // 4*Dh gate rows (permuted)
#define TM     256
#define TN     128
#define KCH    64             // K elems per B pipeline chunk (128B rows)
#define STAGES 3
#define THREADS 512
#define NKT    32             // 2048/64
#define NK16   128            // 2048/16 k16 tiles
// B tile: 128 rows x 128B, 8 chunks of 16B, swizzle c ^= (row&7)
#define B_TILE_BYTES (128 * 128)              // 16384
#define SMEM_TOTAL   (STAGES * B_TILE_BYTES)  // 49152

// ---------------------------------------------------------------------------
// Device scratch: A packed in mma fragment order, B fp16 row-major-K
// ---------------------------------------------------------------------------
// A fragment layout: index ((tile_m*128 + k16)*32 + lane) -> uint4 = {a0,a1,a2,a3}
__device__ uint4  g_Apk[(size_t)(BB / 16) * NK16 * 32];
__device__ __half g_B[(size_t)NROWS * KTOT];

// ---------------------------------------------------------------------------
// PTX helpers (base-ISA only)
// ---------------------------------------------------------------------------
__device__ __forceinline__ uint32_t smem_u32(const void* p) {
    uint32_t a;
    asm("{ .reg .u64 t; cvta.to.shared.u64 t, %1; cvt.u32.u64 %0, t; }"
        : "=r"(a) : "l"(p));
    return a;
}

__device__ __forceinline__ void cp_async16(uint32_t so, const void* gp) {
    asm volatile("cp.async.cg.shared.global [%0], [%1], 16;" :: "r"(so), "l"(gp));
}
#define CP_COMMIT() asm volatile("cp.async.commit_group;" ::: "memory")
#define CP_WAIT1()  asm volatile("cp.async.wait_group 1;" ::: "memory")

#define LDSM_X4(R, ADDR)                                                      \
    asm volatile("ldmatrix.sync.aligned.m8n8.x4.shared.b16 {%0,%1,%2,%3}, [%4];" \
                 : "=r"((R)[0]), "=r"((R)[1]), "=r"((R)[2]), "=r"((R)[3])     \
                 : "r"(ADDR))

// A passed as 4 scalar b32 (from a uint4 fragment register)
#define MMA16816S(C, ax, ay, az, aw, B0, B1)                                  \
    asm volatile("mma.sync.aligned.m16n8k16.row.col.f32.f16.f16.f32 "         \
                 "{%0,%1,%2,%3},{%4,%5,%6,%7},{%8,%9},{%0,%1,%2,%3};"         \
                 : "+f"((C)[0]), "+f"((C)[1]), "+f"((C)[2]), "+f"((C)[3])     \
                 : "r"(ax), "r"(ay), "r"(az), "r"(aw), "r"(B0), "r"(B1))

__device__ __forceinline__ float sigf(float x)   { return 1.0f / (1.0f + __expf(-x)); }
__device__ __forceinline__ float tanh_f(float x) { return 1.0f - 2.0f / (__expf(2.0f * x) + 1.0f); }

// ---------------------------------------------------------------------------
// Prep: pack A into mma fragment order (fp16)
// a0=(g, c,c+1) a1=(g+8, c,c+1) a2=(g, c+8,c+9) a3=(g+8, c+8,c+9), g=lane>>2,
// c=2*(lane&3), rows m=tile*16+g, cols k=k16*16+c. k16 never straddles Di.
// ---------------------------------------------------------------------------
__global__ void pack_Af(const float* __restrict__ X, const float* __restrict__ h0) {
    size_t i = (size_t)blockIdx.x * blockDim.x + threadIdx.x;  // one per uint4
    int lane = (int)(i & 31);
    size_t t2 = i >> 5;
    int k16 = (int)(t2 & (NK16 - 1));
    int tm  = (int)(t2 >> 7);                 // 0..1023
    int g = lane >> 2, c = (lane & 3) * 2;
    int m = tm * 16 + g;
    int k = k16 * 16 + c;
    const float* s0;
    int stride;
    if (k < DI) { s0 = X + (size_t)m * DI + k; stride = DI; }
    else        { s0 = h0 + (size_t)m * DH + (k - DI); stride = DH; }
    const float* s8 = s0 + (size_t)8 * stride;
    __half2 r0(__float2half_rn(s0[0]), __float2half_rn(s0[1]));
    __half2 r1(__float2half_rn(s8[0]), __float2half_rn(s8[1]));
    __half2 r2(__float2half_rn(s0[8]), __float2half_rn(s0[9]));
    __half2 r3(__float2half_rn(s8[8]), __float2half_rn(s8[9]));
    uint4 o;
    o.x = *(uint32_t*)&r0; o.y = *(uint32_t*)&r1;
    o.z = *(uint32_t*)&r2; o.w = *(uint32_t*)&r3;
    g_Apk[i] = o;
}

// Gate permutation matched to the mma.sync C-fragment layout:
// n = gate*1024 + d  ->  np = 64*(d>>4) + 16*((d>>2)&3) + 8*(gate>>1) + 2*(d&3) + (gate&1)
__device__ __forceinline__ int n_to_np(int n) {
    int gate = n >> 10, d = n & 1023;
    return ((d >> 4) << 6) | (((d >> 2) & 3) << 4) | ((gate >> 1) << 3)
           | ((d & 3) << 1) | (gate & 1);
}

// U part (k < 1024): 32x32 tile transpose so both read and write are coalesced.
__global__ void pack_BU(const float* __restrict__ U) {
    __shared__ float tile[32][33];
    int k0 = blockIdx.x * 32, n0 = blockIdx.y * 32;
#pragma unroll
    for (int j = threadIdx.y; j < 32; j += 8)
        tile[j][threadIdx.x] = U[(size_t)(k0 + j) * NROWS + n0 + threadIdx.x];
    __syncthreads();
#pragma unroll
    for (int j = threadIdx.y; j < 32; j += 8) {
        int np = n_to_np(n0 + j);
        g_B[(size_t)np * KTOT + k0 + threadIdx.x] = __float2half_rn(tile[threadIdx.x][j]);
    }
}

// W part (k >= 1024): W[n][k-1024] is already k-contiguous.
__global__ void pack_BW(const float* __restrict__ W) {
    size_t i = (size_t)blockIdx.x * blockDim.x + threadIdx.x;
    int kw = (int)(i & (DH - 1));
    int np = (int)(i >> 10);
    int g = ((np >> 3) & 1) * 2 + (np & 1);
    int d = ((np >> 6) << 4) + (((np >> 4) & 3) << 2) + ((np >> 1) & 3);
    int n = g * DH + d;
    g_B[(size_t)np * KTOT + DI + kw] = __float2half_rn(W[(size_t)n * DH + kw]);
}

// ---------------------------------------------------------------------------
// fp16 GEMM: A via fragment-packed LDG (register ring, prefetch distance 1 kt),
// B via 3-stage cp.async smem pipeline. 512 threads, TM=256 x TN=128,
// warp grid 8(m) x 2(n), warp tile 32x64. MMA:LDSM = 4:1.
// ---------------------------------------------------------------------------
__device__ __forceinline__ void load_B_stage(uint32_t sstage, int kt, int nbase,
                                             int tid) {
    int kk = kt * KCH;
    int r  = tid >> 2;                     // 0..127 (row)
    int cg = (tid & 3) * 2;                // 2 of 8 16B chunks per row
#pragma unroll
    for (int j = 0; j < 2; j++) {
        int c = cg + j;
        uint32_t so = r * 128 + ((c ^ (r & 7)) << 4);
        cp_async16(sstage + so, g_B + (size_t)(nbase + r) * KTOT + kk + c * 8);
    }
    CP_COMMIT();
}

__global__ void __launch_bounds__(THREADS, 1)
lstm_gemm(const float* __restrict__ c0, float* __restrict__ outh,
          float* __restrict__ outc) {
    extern __shared__ char smem[];
    uint32_t sbase = smem_u32(smem);
    int tid  = threadIdx.x;
    int lane = tid & 31, wid = tid >> 5;
    int wm = wid & 7, wn = wid >> 3;        // warp grid 8 (m) x 2 (n)
    int nbase = blockIdx.x * TN;

    // A fragment pointers (one per mt), lane-resolved
    const uint4* pA0 = g_Apk
        + ((size_t)(blockIdx.y * (TM / 16) + wm * 2 + 0) * NK16) * 32 + lane;
    const uint4* pA1 = g_Apk
        + ((size_t)(blockIdx.y * (TM / 16) + wm * 2 + 1) * NK16) * 32 + lane;

    // B ldmatrix lane addressing (8-chunk xor swizzle, 128B rows)
    int brow = wn * 64 + (lane & 7) + ((lane >> 4) & 1) * 8;
    uint32_t bbase = sbase + (uint32_t)brow * 128;
    uint32_t bswz  = (uint32_t)(brow & 7);          // invariant to +16 rows
    uint32_t bbit  = (lane >> 3) & 1;

    float acc[2][8][4];
#pragma unroll
    for (int mt = 0; mt < 2; mt++)
#pragma unroll
        for (int ng = 0; ng < 8; ng++)
#pragma unroll
            for (int j = 0; j < 4; j++) acc[mt][ng][j] = 0.0f;

    // Prologue: B stages 0,1; A fragments for kt=0
    load_B_stage(sbase, 0, nbase, tid);
    load_B_stage(sbase + B_TILE_BYTES, 1, nbase, tid);
    uint4 afrag[4][2];
#pragma unroll
    for (int ks = 0; ks < 4; ks++) {
        afrag[ks][0] = pA0[ks * 32];
        afrag[ks][1] = pA1[ks * 32];
    }

    int stage = 0;
#pragma unroll 1
    for (int kt = 0; kt < NKT; kt++) {
        CP_WAIT1();            // B stage kt resident (issued 2 iterations ago)
        __syncthreads();       // recycled buffer fully consumed by all warps

        if (kt + 2 < NKT) {
            int snext = stage + 2; if (snext >= STAGES) snext -= STAGES;
            load_B_stage(sbase + snext * B_TILE_BYTES, kt + 2, nbase, tid);
        } else {
            CP_COMMIT();       // dummy group keeps wait_group 1 semantics
        }

        uint32_t sa = stage * B_TILE_BYTES;
        int nkt = (kt + 1 < NKT) ? kt + 1 : 0;   // A prefetch target (ring WAR)
#pragma unroll
        for (int ks = 0; ks < 4; ks++) {         // K=64 -> 4 k16 steps
            uint32_t bco = (((2 * ks + bbit) ^ bswz) << 4);
            uint4 a0 = afrag[ks][0];
            uint4 a1 = afrag[ks][1];
#pragma unroll
            for (int gp = 0; gp < 4; gp++) {
                uint32_t b[4];
                LDSM_X4(b, bbase + sa + gp * 16 * 128 + bco);
                MMA16816S(acc[0][2 * gp],     a0.x, a0.y, a0.z, a0.w, b[0], b[1]);
                MMA16816S(acc[1][2 * gp],     a1.x, a1.y, a1.z, a1.w, b[0], b[1]);
                MMA16816S(acc[0][2 * gp + 1], a0.x, a0.y, a0.z, a0.w, b[2], b[3]);
                MMA16816S(acc[1][2 * gp + 1], a1.x, a1.y, a1.z, a1.w, b[2], b[3]);
            }
            // Prefetch next kt's fragment into the slot just consumed
            afrag[ks][0] = pA0[(nkt * 4 + ks) * 32];
            afrag[ks][1] = pA1[(nkt * 4 + ks) * 32];
        }
        stage = stage + 1; if (stage >= STAGES) stage = 0;
    }

    // ---- Fused LSTM epilogue (gates land per-thread via B permutation) ----
    int q = lane & 3;
    int wbg = blockIdx.x * 2 + wn;
    int mbase = blockIdx.y * TM;
#pragma unroll
    for (int mt = 0; mt < 2; mt++) {
#pragma unroll
        for (int e = 0; e < 4; e++) {
#pragma unroll
            for (int rs = 0; rs < 2; rs++) {
                float gi = sigf(acc[mt][2 * e][rs * 2 + 0]);
                float gf = sigf(acc[mt][2 * e][rs * 2 + 1]);
                float gg = tanh_f(acc[mt][2 * e + 1][rs * 2 + 0]);
                float go = sigf(acc[mt][2 * e + 1][rs * 2 + 1]);
                int m = mbase + wm * 32 + mt * 16 + (lane >> 2) + rs * 8;
                int d = wbg * 16 + e * 4 + q;
                size_t idx = (size_t)m * DH + d;
                float c0v = __ldg(&c0[idx]);
                float cn = gf * c0v + gi * gg;
                float hn = go * tanh_f(cn);
                outh[idx] = hn;
                outc[idx] = cn;
            }
        }
    }
}

// ---------------------------------------------------------------------------
// Launch
// ---------------------------------------------------------------------------
extern "C" void kernel_launch(void* const* d_in, const int* in_sizes, int n_in,
                              void* d_out, int out_size) {
    const float* X  = (const float*)d_in[0];
    const float* h0 = (const float*)d_in[1];
    const float* c0 = (const float*)d_in[2];
    const float* U  = (const float*)d_in[3];
    const float* W  = (const float*)d_in[4];
    float* outh = (float*)d_out;
    float* outc = outh + (size_t)BB * DH;

    pack_Af<<<(int)(((size_t)(BB / 16) * NK16 * 32) / 256), 256>>>(X, h0);
    dim3 gbu(DI / 32, NROWS / 32);
    pack_BU<<<gbu, dim3(32, 8)>>>(U);
    pack_BW<<<(NROWS * DH) / 256, 256>>>(W);

    cudaFuncSetAttribute(lstm_gemm, cudaFuncAttributeMaxDynamicSharedMemorySize,
                         SMEM_TOTAL);
    dim3 grid(NROWS / TN, BB / TM);
    lstm_gemm<<<grid, THREADS, SMEM_TOTAL>>>(c0, outh, outc);
}